// round 5
// baseline (speedup 1.0000x reference)
#include <cuda_runtime.h>
#include <math.h>

// Problem constants (fixed by reference)
#define BB      2
#define TT      8192
#define EE      256
#define CSZ     128
#define NN      64        // TT / CSZ
#define NSEL    7         // K - 1
#define LEXT    1024      // K * CS
#define EPSF    1e-6f

#define KT      32        // k-tile
#define LDT     132       // smem leading dim (132*4B % 16B == 0, depolarizes banks)

// Scratch (static device globals — no allocation)
__device__ float g_cn[(size_t)BB * TT * EE];        // normalized rows, 16 MB
__device__ float g_scores[BB * NN * NN];
__device__ int   g_selidx[BB * NN * NSEL];
__device__ float g_selw[BB * NN * NSEL];

// ---------------------------------------------------------------------------
// Kernel A: row-normalize.  One warp per row (row length EE=256).
// ---------------------------------------------------------------------------
__global__ __launch_bounds__(256) void normalize_kernel(const float* __restrict__ x) {
    int row  = blockIdx.x * 8 + (threadIdx.x >> 5);
    int lane = threadIdx.x & 31;
    const float4* xr = (const float4*)(x + (size_t)row * EE);
    float4 v0 = xr[lane];
    float4 v1 = xr[lane + 32];
    float ss = v0.x*v0.x + v0.y*v0.y + v0.z*v0.z + v0.w*v0.w
             + v1.x*v1.x + v1.y*v1.y + v1.z*v1.z + v1.w*v1.w;
    #pragma unroll
    for (int off = 16; off; off >>= 1)
        ss += __shfl_xor_sync(0xffffffffu, ss, off);
    float inv = 1.0f / (sqrtf(ss) + EPSF);
    float4* cr = (float4*)(g_cn + (size_t)row * EE);
    v0.x *= inv; v0.y *= inv; v0.z *= inv; v0.w *= inv;
    v1.x *= inv; v1.y *= inv; v1.z *= inv; v1.w *= inv;
    cr[lane]      = v0;
    cr[lane + 32] = v1;
}

// ---------------------------------------------------------------------------
// Kernel B: pair scores.  CTA = (j, i, b), j < i.
// C[c,d] = cn_i[c,:] . cn_j[d,:]  (128x128x256), then score = sum_c max_d C.
// ---------------------------------------------------------------------------
__global__ __launch_bounds__(256) void score_kernel() {
    int j = blockIdx.x, i = blockIdx.y, b = blockIdx.z;
    if (j >= i) return;

    __shared__ float As[KT * LDT];
    __shared__ float Bs[KT * LDT];
    __shared__ float part[16];

    int tid = threadIdx.x;
    int tx = tid & 15, ty = tid >> 4;

    const float* Abase = g_cn + ((size_t)b * TT + (size_t)i * CSZ) * EE;
    const float* Bbase = g_cn + ((size_t)b * TT + (size_t)j * CSZ) * EE;

    float acc[8][8];
    #pragma unroll
    for (int u = 0; u < 8; u++)
        #pragma unroll
        for (int v = 0; v < 8; v++) acc[u][v] = 0.0f;

    for (int k0 = 0; k0 < EE; k0 += KT) {
        __syncthreads();
        // load both tiles transposed: As[kk][row], Bs[kk][row]
        #pragma unroll
        for (int r = 0; r < 4; r++) {
            int idx = tid + 256 * r;
            int row = idx >> 3;
            int c4  = idx & 7;
            float4 va = *(const float4*)(Abase + (size_t)row * EE + k0 + c4 * 4);
            As[(c4*4+0)*LDT + row] = va.x;
            As[(c4*4+1)*LDT + row] = va.y;
            As[(c4*4+2)*LDT + row] = va.z;
            As[(c4*4+3)*LDT + row] = va.w;
            float4 vb = *(const float4*)(Bbase + (size_t)row * EE + k0 + c4 * 4);
            Bs[(c4*4+0)*LDT + row] = vb.x;
            Bs[(c4*4+1)*LDT + row] = vb.y;
            Bs[(c4*4+2)*LDT + row] = vb.z;
            Bs[(c4*4+3)*LDT + row] = vb.w;
        }
        __syncthreads();
        #pragma unroll 8
        for (int kk = 0; kk < KT; kk++) {
            float a[8], bb[8];
            *(float4*)&a[0]  = *(const float4*)&As[kk*LDT + ty*4];
            *(float4*)&a[4]  = *(const float4*)&As[kk*LDT + 64 + ty*4];
            *(float4*)&bb[0] = *(const float4*)&Bs[kk*LDT + tx*4];
            *(float4*)&bb[4] = *(const float4*)&Bs[kk*LDT + 64 + tx*4];
            #pragma unroll
            for (int u = 0; u < 8; u++)
                #pragma unroll
                for (int v = 0; v < 8; v++)
                    acc[u][v] = fmaf(a[u], bb[v], acc[u][v]);
        }
    }

    // per-row max over this thread's 8 cols
    float m[8];
    #pragma unroll
    for (int u = 0; u < 8; u++) {
        float mm = acc[u][0];
        #pragma unroll
        for (int v = 1; v < 8; v++) mm = fmaxf(mm, acc[u][v]);
        m[u] = mm;
    }
    // max across the 16 tx lanes (same rows)
    #pragma unroll
    for (int s = 1; s <= 8; s <<= 1)
        #pragma unroll
        for (int u = 0; u < 8; u++)
            m[u] = fmaxf(m[u], __shfl_xor_sync(0xffffffffu, m[u], s));

    float partial = 0.0f;
    #pragma unroll
    for (int u = 0; u < 8; u++) partial += m[u];
    if (tx == 0) part[ty] = partial;
    __syncthreads();
    if (tid == 0) {
        float sc = 0.0f;
        #pragma unroll
        for (int u = 0; u < 16; u++) sc += part[u];
        g_scores[((size_t)b * NN + i) * NN + j] = sc;
    }
}

// ---------------------------------------------------------------------------
// Kernel C: top-7, weights, slot arrangement.  One warp per (b, i).
// ---------------------------------------------------------------------------
__global__ void topk_kernel() {
    int bi = blockIdx.x;
    int b = bi / NN, i = bi % NN;
    int lane = threadIdx.x;

    const float* srow = g_scores + ((size_t)b * NN + i) * NN;
    int j0 = lane, j1 = lane + 32;
    float v0 = (j0 < i) ? srow[j0] : -1e9f;
    float v1 = (j1 < i) ? srow[j1] : -1e9f;

    float vals[NSEL]; int idx[NSEL];
    for (int s = 0; s < NSEL; s++) {
        float bv; int bidx;
        if (v0 >= v1) { bv = v0; bidx = j0; } else { bv = v1; bidx = j1; }
        #pragma unroll
        for (int off = 16; off; off >>= 1) {
            float ov = __shfl_xor_sync(0xffffffffu, bv, off);
            int   oi = __shfl_xor_sync(0xffffffffu, bidx, off);
            if (ov > bv || (ov == bv && oi < bidx)) { bv = ov; bidx = oi; }
        }
        vals[s] = bv; idx[s] = bidx;
        if (j0 == bidx) v0 = -3.402823466e38f;
        if (j1 == bidx) v1 = -3.402823466e38f;
    }

    if (lane == 0) {
        int num_sel = (i < NSEL) ? i : NSEL;
        int vs = num_sel - 1;
        if (vs < 0) vs = 0;
        float vmin = vals[vs];
        float w[NSEL];
        for (int s = 0; s < NSEL; s++)
            w[s] = (s < num_sel) ? vals[s] / (vmin + EPSF) : 0.0f;
        int shift = NSEL - i; if (shift < 0) shift = 0;
        for (int t = 0; t < NSEL; t++) {
            int dst = ((size_t)b * NN + i) * NSEL + t;
            if (t >= shift) {
                g_selidx[dst] = idx[t - shift];
                g_selw[dst]   = w[t - shift];
            } else {
                g_selidx[dst] = 0;
                g_selw[dst]   = 0.0f;
            }
        }
    }
}

// ---------------------------------------------------------------------------
// Kernel D: out[b,n] = down_proj @ ext + chunk.  CTA = (e-half, n, b).
// ext gathered on the fly: slot t<7 -> w[t]*chunk[idx[t]], slot 7 -> chunk n.
// ---------------------------------------------------------------------------
__global__ __launch_bounds__(256) void out_kernel(const float* __restrict__ x,
                                                  const float* __restrict__ dp,
                                                  float* __restrict__ out) {
    int eh = blockIdx.x, n = blockIdx.y, b = blockIdx.z;

    __shared__ float As[KT * LDT];
    __shared__ float Bs[KT * LDT];
    __shared__ int   s_idx[8];
    __shared__ float s_w[8];

    int tid = threadIdx.x;
    if (tid < NSEL) {
        s_idx[tid] = g_selidx[((size_t)b * NN + n) * NSEL + tid];
        s_w[tid]   = g_selw[((size_t)b * NN + n) * NSEL + tid];
    }
    if (tid == NSEL) { s_idx[NSEL] = n; s_w[NSEL] = 1.0f; }
    __syncthreads();

    int tx = tid & 15, ty = tid >> 4;
    int e0 = eh * 128;
    const float* xb = x + (size_t)b * TT * EE;

    float acc[8][8];
    #pragma unroll
    for (int u = 0; u < 8; u++)
        #pragma unroll
        for (int v = 0; v < 8; v++) acc[u][v] = 0.0f;

    for (int kt = 0; kt < LEXT / KT; kt++) {
        int l0   = kt * KT;
        int slot = l0 >> 7;
        int c2   = l0 & 127;
        const float* src = xb + ((size_t)s_idx[slot] * CSZ + c2) * EE + e0;
        float w = s_w[slot];

        __syncthreads();
        // B tile: [32 l][128 e], weight applied at load; no transpose needed
        #pragma unroll
        for (int r = 0; r < 4; r++) {
            int idx = tid + 256 * r;
            int kk = idx >> 5;
            int c4 = idx & 31;
            float4 v = *(const float4*)(src + (size_t)kk * EE + c4 * 4);
            v.x *= w; v.y *= w; v.z *= w; v.w *= w;
            *(float4*)&Bs[kk * LDT + c4 * 4] = v;
        }
        // A tile: down_proj [128 c][32 l] transposed -> As[kk][c]
        #pragma unroll
        for (int r = 0; r < 4; r++) {
            int idx = tid + 256 * r;
            int row = idx >> 3;
            int c4  = idx & 7;
            float4 v = *(const float4*)(dp + (size_t)row * LEXT + l0 + c4 * 4);
            As[(c4*4+0)*LDT + row] = v.x;
            As[(c4*4+1)*LDT + row] = v.y;
            As[(c4*4+2)*LDT + row] = v.z;
            As[(c4*4+3)*LDT + row] = v.w;
        }
        __syncthreads();
        #pragma unroll 8
        for (int kk = 0; kk < KT; kk++) {
            float a[8], bb[8];
            *(float4*)&a[0]  = *(const float4*)&As[kk*LDT + ty*4];
            *(float4*)&a[4]  = *(const float4*)&As[kk*LDT + 64 + ty*4];
            *(float4*)&bb[0] = *(const float4*)&Bs[kk*LDT + tx*4];
            *(float4*)&bb[4] = *(const float4*)&Bs[kk*LDT + 64 + tx*4];
            #pragma unroll
            for (int u = 0; u < 8; u++)
                #pragma unroll
                for (int v = 0; v < 8; v++)
                    acc[u][v] = fmaf(a[u], bb[v], acc[u][v]);
        }
    }

    // epilogue: add residual (chunk n) and store
    #pragma unroll
    for (int rh = 0; rh < 2; rh++) {
        #pragma unroll
        for (int u = 0; u < 4; u++) {
            int r = rh * 64 + ty * 4 + u;
            const float* resrow = xb + ((size_t)n * CSZ + r) * EE + e0;
            float* orow = out + ((size_t)b * TT + (size_t)n * CSZ + r) * EE + e0;
            #pragma unroll
            for (int ch = 0; ch < 2; ch++) {
                int c = ch * 64 + tx * 4;
                float4 res = *(const float4*)(resrow + c);
                float4 o;
                o.x = acc[rh*4+u][ch*4+0] + res.x;
                o.y = acc[rh*4+u][ch*4+1] + res.y;
                o.z = acc[rh*4+u][ch*4+2] + res.z;
                o.w = acc[rh*4+u][ch*4+3] + res.w;
                *(float4*)(orow + c) = o;
            }
        }
    }
}

// ---------------------------------------------------------------------------
extern "C" void kernel_launch(void* const* d_in, const int* in_sizes, int n_in,
                              void* d_out, int out_size) {
    // identify inputs by size to be robust to ordering
    const float* x  = (const float*)d_in[0];
    const float* dp = (const float*)d_in[1];
    if (in_sizes[0] == CSZ * LEXT) {  // down_proj came first
        dp = (const float*)d_in[0];
        x  = (const float*)d_in[1];
    }
    float* out = (float*)d_out;

    normalize_kernel<<<(BB * TT) / 8, 256>>>(x);
    score_kernel<<<dim3(NN, NN, BB), 256>>>();
    topk_kernel<<<BB * NN, 32>>>();
    out_kernel<<<dim3(2, NN, BB), 256>>>(x, dp, out);
}

// round 8
// speedup vs baseline: 1.8615x; 1.8615x over previous
#include <cuda_runtime.h>
#include <cuda_bf16.h>
#include <math.h>
#include <stdint.h>

// Problem constants (fixed by reference)
#define BB      2
#define TT      8192
#define EE      256
#define CSZ     128
#define NN      64        // TT / CSZ
#define NSEL    7         // K - 1
#define LEXT    1024      // K * CS
#define EPSF    1e-6f

#define KT      32        // k-tile (fp32 out_kernel)
#define LDT     132       // smem leading dim for fp32 GEMM

// score kernel smem geometry
#define LDB     40                    // bf16 row stride of staged tiles
#define TILE_B  (128 * LDB * 2)       // 10240 bytes per tile
#define STG     (4 * TILE_B)          // 40960 bytes per stage (Ah,Al,Bh,Bl)
#define OFF_MAX (2 * STG)             // 81920: float smax[4][128]
#define OFF_PART (OFF_MAX + 4 * 128 * 4)
#define SCORE_SMEM (OFF_PART + 64)

// ---------------------------------------------------------------------------
// Scratch (static device globals — no allocation)
// ---------------------------------------------------------------------------
__device__ __nv_bfloat16 g_hi[(size_t)BB * TT * EE];   // bf16(cn), 8 MB
__device__ __nv_bfloat16 g_lo[(size_t)BB * TT * EE];   // bf16(cn - hi), 8 MB
__device__ float g_scores[BB * NN * NN];
__device__ int   g_selidx[BB * NN * NSEL];
__device__ float g_selw[BB * NN * NSEL];

// ---------------------------------------------------------------------------
// Base-PTX helpers (no 'a'-target instructions!)
// ---------------------------------------------------------------------------
__device__ __forceinline__ uint32_t smem_u32(const void* p) {
    uint32_t a;
    asm("{ .reg .u64 t; cvta.to.shared.u64 t, %1; cvt.u32.u64 %0, t; }"
        : "=r"(a) : "l"(p));
    return a;
}
__device__ __forceinline__ void cp16(uint32_t dst, const void* src) {
    asm volatile("cp.async.cg.shared.global [%0], [%1], 16;" :: "r"(dst), "l"(src));
}
__device__ __forceinline__ void cp_commit() {
    asm volatile("cp.async.commit_group;" ::: "memory");
}
template<int N> __device__ __forceinline__ void cp_wait() {
    asm volatile("cp.async.wait_group %0;" :: "n"(N) : "memory");
}
__device__ __forceinline__ void ldmx4(uint32_t* r, uint32_t addr) {
    asm volatile("ldmatrix.sync.aligned.m8n8.x4.shared.b16 {%0,%1,%2,%3}, [%4];"
                 : "=r"(r[0]), "=r"(r[1]), "=r"(r[2]), "=r"(r[3]) : "r"(addr));
}
__device__ __forceinline__ void mma16816(float* c, const uint32_t* a, const uint32_t* b) {
    asm volatile("mma.sync.aligned.m16n8k16.row.col.f32.bf16.bf16.f32 "
                 "{%0,%1,%2,%3}, {%4,%5,%6,%7}, {%8,%9}, {%0,%1,%2,%3};"
                 : "+f"(c[0]), "+f"(c[1]), "+f"(c[2]), "+f"(c[3])
                 : "r"(a[0]), "r"(a[1]), "r"(a[2]), "r"(a[3]),
                   "r"(b[0]), "r"(b[1]));
}

// ---------------------------------------------------------------------------
// Kernel A: row-normalize + hi/lo bf16 split.  One warp per row.
// ---------------------------------------------------------------------------
__global__ __launch_bounds__(256) void normalize_kernel(const float* __restrict__ x) {
    int row  = blockIdx.x * 8 + (threadIdx.x >> 5);
    int lane = threadIdx.x & 31;
    const float4* xr = (const float4*)(x + (size_t)row * EE);
    float4 v0 = xr[lane];
    float4 v1 = xr[lane + 32];
    float ss = v0.x*v0.x + v0.y*v0.y + v0.z*v0.z + v0.w*v0.w
             + v1.x*v1.x + v1.y*v1.y + v1.z*v1.z + v1.w*v1.w;
    #pragma unroll
    for (int off = 16; off; off >>= 1)
        ss += __shfl_xor_sync(0xffffffffu, ss, off);
    float inv = 1.0f / (sqrtf(ss) + EPSF);

    #pragma unroll
    for (int g = 0; g < 2; g++) {
        float4 v = g ? v1 : v0;
        float f[4] = {v.x*inv, v.y*inv, v.z*inv, v.w*inv};
        unsigned short h[4], l[4];
        #pragma unroll
        for (int q = 0; q < 4; q++) {
            __nv_bfloat16 hb = __float2bfloat16(f[q]);
            __nv_bfloat16 lb = __float2bfloat16(f[q] - __bfloat162float(hb));
            h[q] = *reinterpret_cast<unsigned short*>(&hb);
            l[q] = *reinterpret_cast<unsigned short*>(&lb);
        }
        uint2 hv = make_uint2((uint32_t)h[0] | ((uint32_t)h[1] << 16),
                              (uint32_t)h[2] | ((uint32_t)h[3] << 16));
        uint2 lv = make_uint2((uint32_t)l[0] | ((uint32_t)l[1] << 16),
                              (uint32_t)l[2] | ((uint32_t)l[3] << 16));
        size_t e = (size_t)row * EE + ((size_t)lane + (g ? 32 : 0)) * 4;
        *(uint2*)(g_hi + e) = hv;
        *(uint2*)(g_lo + e) = lv;
    }
}

// ---------------------------------------------------------------------------
// Kernel B: pair scores via mma.sync bf16 hi/lo (3-product fp32 emulation).
// CTA = (j, i, b), j < i.  C = cn_i @ cn_j^T (128x128x256), score = sum_c max_d C.
// 8 warps in 2(M) x 4(N); each warp computes 64x32 of C.
// ---------------------------------------------------------------------------
__global__ __launch_bounds__(256) void score_kernel() {
    int j = blockIdx.x, i = blockIdx.y, b = blockIdx.z;
    if (j >= i) return;

    extern __shared__ char sm[];
    uint32_t smb = smem_u32(sm);
    int tid = threadIdx.x, lane = tid & 31, wid = tid >> 5;
    int wm = wid & 1, wn = wid >> 1;

    const __nv_bfloat16* srcs[4];
    srcs[0] = g_hi + ((size_t)b * TT + (size_t)i * CSZ) * EE;   // Ah
    srcs[1] = g_lo + ((size_t)b * TT + (size_t)i * CSZ) * EE;   // Al
    srcs[2] = g_hi + ((size_t)b * TT + (size_t)j * CSZ) * EE;   // Bh
    srcs[3] = g_lo + ((size_t)b * TT + (size_t)j * CSZ) * EE;   // Bl

    float acc[4][4][4];
    #pragma unroll
    for (int mf = 0; mf < 4; mf++)
        #pragma unroll
        for (int nf = 0; nf < 4; nf++)
            #pragma unroll
            for (int q = 0; q < 4; q++) acc[mf][nf][q] = 0.0f;

    // ldmatrix per-lane address components
    int g8  = lane & 7, sel = lane >> 3;
    int a_row = g8 + ((sel & 1) ? 8 : 0);       // A: m0 rows+0 k+0, m1 rows+8 k+0, m2 rows+0 k+8, m3 rows+8 k+8
    int a_col = (sel & 2) ? 8 : 0;
    int b_row = g8 + ((sel >= 2) ? 8 : 0);      // B: m0 n+0 k+0, m1 n+0 k+8, m2 n+8 k+0, m3 n+8 k+8
    int b_col = (sel & 1) ? 8 : 0;

    // stage loader: 4 tiles of 128 rows x 32 bf16 (64 B/row = 4 x 16B chunks)
    auto issue_stage = [&](int stage, int kt) {
        uint32_t sbase = smb + stage * STG;
        int k0 = kt * 32;
        #pragma unroll
        for (int t = 0; t < 8; t++) {
            int chunk = tid + t * 256;          // 0..2047
            int tile  = chunk >> 9;             // 0..3
            int within = chunk & 511;
            int row = within >> 2;
            int seg = within & 3;
            cp16(sbase + tile * TILE_B + row * (LDB * 2) + seg * 16,
                 srcs[tile] + (size_t)row * EE + k0 + seg * 8);
        }
    };

    issue_stage(0, 0);
    cp_commit();

    for (int kt = 0; kt < 8; kt++) {
        int buf = kt & 1;
        if (kt < 7) {
            issue_stage(buf ^ 1, kt + 1);
            cp_commit();
            cp_wait<1>();
        } else {
            cp_wait<0>();
        }
        __syncthreads();

        uint32_t bAh = smb + buf * STG;
        uint32_t bAl = bAh + TILE_B;
        uint32_t bBh = bAh + 2 * TILE_B;
        uint32_t bBl = bAh + 3 * TILE_B;

        #pragma unroll
        for (int kk = 0; kk < 32; kk += 16) {
            uint32_t aH[4][4], aL[4][4], bH[4][2], bL[4][2];
            #pragma unroll
            for (int mf = 0; mf < 4; mf++) {
                uint32_t off = (uint32_t)((wm * 64 + mf * 16 + a_row) * (LDB * 2)
                                          + (kk + a_col) * 2);
                ldmx4(aH[mf], bAh + off);
                ldmx4(aL[mf], bAl + off);
            }
            #pragma unroll
            for (int p = 0; p < 2; p++) {
                uint32_t off = (uint32_t)((wn * 32 + p * 16 + b_row) * (LDB * 2)
                                          + (kk + b_col) * 2);
                uint32_t r[4];
                ldmx4(r, bBh + off);
                bH[2*p][0] = r[0]; bH[2*p][1] = r[1];
                bH[2*p+1][0] = r[2]; bH[2*p+1][1] = r[3];
                ldmx4(r, bBl + off);
                bL[2*p][0] = r[0]; bL[2*p][1] = r[1];
                bL[2*p+1][0] = r[2]; bL[2*p+1][1] = r[3];
            }
            #pragma unroll
            for (int mf = 0; mf < 4; mf++)
                #pragma unroll
                for (int nf = 0; nf < 4; nf++) {
                    mma16816(acc[mf][nf], aH[mf], bH[nf]);
                    mma16816(acc[mf][nf], aH[mf], bL[nf]);
                    mma16816(acc[mf][nf], aL[mf], bH[nf]);
                }
        }
        __syncthreads();
    }

    // ---- epilogue: score = sum_rows( max_cols C ) ----
    float* smax = (float*)(sm + OFF_MAX);
    #pragma unroll
    for (int mf = 0; mf < 4; mf++)
        #pragma unroll
        for (int h = 0; h < 2; h++) {
            float v = -3.402823466e38f;
            #pragma unroll
            for (int nf = 0; nf < 4; nf++) {
                v = fmaxf(v, acc[mf][nf][2*h]);
                v = fmaxf(v, acc[mf][nf][2*h + 1]);
            }
            v = fmaxf(v, __shfl_xor_sync(0xffffffffu, v, 1));
            v = fmaxf(v, __shfl_xor_sync(0xffffffffu, v, 2));
            if ((lane & 3) == 0)
                smax[wn * 128 + wm * 64 + mf * 16 + h * 8 + (lane >> 2)] = v;
        }
    __syncthreads();

    float ssum = 0.0f;
    if (tid < 128) {
        float v = smax[tid];
        v = fmaxf(v, smax[128 + tid]);
        v = fmaxf(v, smax[256 + tid]);
        v = fmaxf(v, smax[384 + tid]);
        ssum = v;
        #pragma unroll
        for (int off = 16; off; off >>= 1)
            ssum += __shfl_xor_sync(0xffffffffu, ssum, off);
        float* part = (float*)(sm + OFF_PART);
        if (lane == 0) part[wid] = ssum;
    }
    __syncthreads();
    if (tid == 0) {
        float* part = (float*)(sm + OFF_PART);
        g_scores[((size_t)b * NN + i) * NN + j] = part[0] + part[1] + part[2] + part[3];
    }
}

// ---------------------------------------------------------------------------
// Kernel C: top-7, weights, slot arrangement.  One warp per (b, i).
// ---------------------------------------------------------------------------
__global__ void topk_kernel() {
    int bi = blockIdx.x;
    int b = bi / NN, i = bi % NN;
    int lane = threadIdx.x;

    const float* srow = g_scores + ((size_t)b * NN + i) * NN;
    int j0 = lane, j1 = lane + 32;
    float v0 = (j0 < i) ? srow[j0] : -1e9f;
    float v1 = (j1 < i) ? srow[j1] : -1e9f;

    float vals[NSEL]; int idx[NSEL];
    for (int s = 0; s < NSEL; s++) {
        float bv; int bidx;
        if (v0 >= v1) { bv = v0; bidx = j0; } else { bv = v1; bidx = j1; }
        #pragma unroll
        for (int off = 16; off; off >>= 1) {
            float ov = __shfl_xor_sync(0xffffffffu, bv, off);
            int   oi = __shfl_xor_sync(0xffffffffu, bidx, off);
            if (ov > bv || (ov == bv && oi < bidx)) { bv = ov; bidx = oi; }
        }
        vals[s] = bv; idx[s] = bidx;
        if (j0 == bidx) v0 = -3.402823466e38f;
        if (j1 == bidx) v1 = -3.402823466e38f;
    }

    if (lane == 0) {
        int num_sel = (i < NSEL) ? i : NSEL;
        int vs = num_sel - 1;
        if (vs < 0) vs = 0;
        float vmin = vals[vs];
        float w[NSEL];
        for (int s = 0; s < NSEL; s++)
            w[s] = (s < num_sel) ? vals[s] / (vmin + EPSF) : 0.0f;
        int shift = NSEL - i; if (shift < 0) shift = 0;
        for (int t = 0; t < NSEL; t++) {
            int dst = ((size_t)b * NN + i) * NSEL + t;
            if (t >= shift) {
                g_selidx[dst] = idx[t - shift];
                g_selw[dst]   = w[t - shift];
            } else {
                g_selidx[dst] = 0;
                g_selw[dst]   = 0.0f;
            }
        }
    }
}

// ---------------------------------------------------------------------------
// Kernel D: out[b,n] = down_proj @ ext + chunk.  CTA = (e-half, n, b).
// ---------------------------------------------------------------------------
__global__ __launch_bounds__(256) void out_kernel(const float* __restrict__ x,
                                                  const float* __restrict__ dp,
                                                  float* __restrict__ out) {
    int eh = blockIdx.x, n = blockIdx.y, b = blockIdx.z;

    __shared__ float As[KT * LDT];
    __shared__ float Bs[KT * LDT];
    __shared__ int   s_idx[8];
    __shared__ float s_w[8];

    int tid = threadIdx.x;
    if (tid < NSEL) {
        s_idx[tid] = g_selidx[((size_t)b * NN + n) * NSEL + tid];
        s_w[tid]   = g_selw[((size_t)b * NN + n) * NSEL + tid];
    }
    if (tid == NSEL) { s_idx[NSEL] = n; s_w[NSEL] = 1.0f; }
    __syncthreads();

    int tx = tid & 15, ty = tid >> 4;
    int e0 = eh * 128;
    const float* xb = x + (size_t)b * TT * EE;

    float acc[8][8];
    #pragma unroll
    for (int u = 0; u < 8; u++)
        #pragma unroll
        for (int v = 0; v < 8; v++) acc[u][v] = 0.0f;

    for (int kt = 0; kt < LEXT / KT; kt++) {
        int l0   = kt * KT;
        int slot = l0 >> 7;
        int c2   = l0 & 127;
        const float* src = xb + ((size_t)s_idx[slot] * CSZ + c2) * EE + e0;
        float w = s_w[slot];

        __syncthreads();
        #pragma unroll
        for (int r = 0; r < 4; r++) {
            int idx = tid + 256 * r;
            int kk = idx >> 5;
            int c4 = idx & 31;
            float4 v = *(const float4*)(src + (size_t)kk * EE + c4 * 4);
            v.x *= w; v.y *= w; v.z *= w; v.w *= w;
            *(float4*)&Bs[kk * LDT + c4 * 4] = v;
        }
        #pragma unroll
        for (int r = 0; r < 4; r++) {
            int idx = tid + 256 * r;
            int row = idx >> 3;
            int c4  = idx & 7;
            float4 v = *(const float4*)(dp + (size_t)row * LEXT + l0 + c4 * 4);
            As[(c4*4+0)*LDT + row] = v.x;
            As[(c4*4+1)*LDT + row] = v.y;
            As[(c4*4+2)*LDT + row] = v.z;
            As[(c4*4+3)*LDT + row] = v.w;
        }
        __syncthreads();
        #pragma unroll 8
        for (int kk = 0; kk < KT; kk++) {
            float a[8], bb[8];
            *(float4*)&a[0]  = *(const float4*)&As[kk*LDT + ty*4];
            *(float4*)&a[4]  = *(const float4*)&As[kk*LDT + 64 + ty*4];
            *(float4*)&bb[0] = *(const float4*)&Bs[kk*LDT + tx*4];
            *(float4*)&bb[4] = *(const float4*)&Bs[kk*LDT + 64 + tx*4];
            #pragma unroll
            for (int u = 0; u < 8; u++)
                #pragma unroll
                for (int v = 0; v < 8; v++)
                    acc[u][v] = fmaf(a[u], bb[v], acc[u][v]);
        }
    }

    #pragma unroll
    for (int rh = 0; rh < 2; rh++) {
        #pragma unroll
        for (int u = 0; u < 4; u++) {
            int r = rh * 64 + ty * 4 + u;
            const float* resrow = xb + ((size_t)n * CSZ + r) * EE + e0;
            float* orow = out + ((size_t)b * TT + (size_t)n * CSZ + r) * EE + e0;
            #pragma unroll
            for (int ch = 0; ch < 2; ch++) {
                int c = ch * 64 + tx * 4;
                float4 res = *(const float4*)(resrow + c);
                float4 o;
                o.x = acc[rh*4+u][ch*4+0] + res.x;
                o.y = acc[rh*4+u][ch*4+1] + res.y;
                o.z = acc[rh*4+u][ch*4+2] + res.z;
                o.w = acc[rh*4+u][ch*4+3] + res.w;
                *(float4*)(orow + c) = o;
            }
        }
    }
}

// ---------------------------------------------------------------------------
extern "C" void kernel_launch(void* const* d_in, const int* in_sizes, int n_in,
                              void* d_out, int out_size) {
    const float* x  = (const float*)d_in[0];
    const float* dp = (const float*)d_in[1];
    if (in_sizes[0] == CSZ * LEXT) {  // down_proj came first
        dp = (const float*)d_in[0];
        x  = (const float*)d_in[1];
    }
    float* out = (float*)d_out;

    cudaFuncSetAttribute(score_kernel,
                         cudaFuncAttributeMaxDynamicSharedMemorySize, SCORE_SMEM);

    normalize_kernel<<<(BB * TT) / 8, 256>>>(x);
    score_kernel<<<dim3(NN, NN, BB), 256, SCORE_SMEM>>>();
    topk_kernel<<<BB * NN, 32>>>();
    out_kernel<<<dim3(2, NN, BB), 256>>>(x, dp, out);
}

// round 9
// speedup vs baseline: 2.2671x; 1.2179x over previous
#include <cuda_runtime.h>
#include <cuda_bf16.h>
#include <math.h>
#include <stdint.h>

// Problem constants (fixed by reference)
#define BB      2
#define TT      8192
#define EE      256
#define CSZ     128
#define NN      64        // TT / CSZ
#define NSEL    7         // K - 1
#define LEXT    1024      // K * CS
#define EPSF    1e-6f

// score kernel smem geometry
#define LDB     40                    // bf16 row stride of staged [rows][k] tiles
#define TILE_B  (128 * LDB * 2)       // 10240 bytes per tile
#define STG     (4 * TILE_B)          // 40960 bytes per stage (Ah,Al,Bh,Bl)
#define OFF_MAX (2 * STG)             // 81920: float smax[4][128]
#define OFF_PART (OFF_MAX + 4 * 128 * 4)
#define SCORE_SMEM (OFF_PART + 64)

// out kernel smem geometry
#define LDE      136                  // bf16 row stride of [k=32][e=128] B tiles
#define OA_TILE  (128 * LDB * 2)      // 10240: A tile (128 c x 32 l)
#define OB_TILE  (32 * LDE * 2)       // 8704:  B tile (32 l x 128 e)
#define OSTG     (2 * OA_TILE + 2 * OB_TILE)   // 37888 per stage
#define OUT_SMEM (2 * OSTG + 64)

// ---------------------------------------------------------------------------
// Scratch (static device globals — no allocation)
// ---------------------------------------------------------------------------
__device__ __nv_bfloat16 g_hi[(size_t)BB * TT * EE];   // bf16(cn), 8 MB
__device__ __nv_bfloat16 g_lo[(size_t)BB * TT * EE];   // bf16(cn - hi), 8 MB
__device__ __nv_bfloat16 g_xhi[(size_t)BB * TT * EE];  // bf16(x), 8 MB
__device__ __nv_bfloat16 g_xlo[(size_t)BB * TT * EE];  // bf16(x - xhi), 8 MB
__device__ float g_scores[BB * NN * NN];
__device__ int   g_selidx[BB * NN * NSEL];
__device__ float g_selw[BB * NN * NSEL];

// ---------------------------------------------------------------------------
// Base-PTX helpers (no 'a'-target instructions!)
// ---------------------------------------------------------------------------
__device__ __forceinline__ uint32_t smem_u32(const void* p) {
    uint32_t a;
    asm("{ .reg .u64 t; cvta.to.shared.u64 t, %1; cvt.u32.u64 %0, t; }"
        : "=r"(a) : "l"(p));
    return a;
}
__device__ __forceinline__ void cp16(uint32_t dst, const void* src) {
    asm volatile("cp.async.cg.shared.global [%0], [%1], 16;" :: "r"(dst), "l"(src));
}
__device__ __forceinline__ void cp_commit() {
    asm volatile("cp.async.commit_group;" ::: "memory");
}
template<int N> __device__ __forceinline__ void cp_wait() {
    asm volatile("cp.async.wait_group %0;" :: "n"(N) : "memory");
}
__device__ __forceinline__ void ldmx4(uint32_t* r, uint32_t addr) {
    asm volatile("ldmatrix.sync.aligned.m8n8.x4.shared.b16 {%0,%1,%2,%3}, [%4];"
                 : "=r"(r[0]), "=r"(r[1]), "=r"(r[2]), "=r"(r[3]) : "r"(addr));
}
__device__ __forceinline__ void ldmx4t(uint32_t* r, uint32_t addr) {
    asm volatile("ldmatrix.sync.aligned.m8n8.x4.trans.shared.b16 {%0,%1,%2,%3}, [%4];"
                 : "=r"(r[0]), "=r"(r[1]), "=r"(r[2]), "=r"(r[3]) : "r"(addr));
}
__device__ __forceinline__ void mma16816(float* c, const uint32_t* a, const uint32_t* b) {
    asm volatile("mma.sync.aligned.m16n8k16.row.col.f32.bf16.bf16.f32 "
                 "{%0,%1,%2,%3}, {%4,%5,%6,%7}, {%8,%9}, {%0,%1,%2,%3};"
                 : "+f"(c[0]), "+f"(c[1]), "+f"(c[2]), "+f"(c[3])
                 : "r"(a[0]), "r"(a[1]), "r"(a[2]), "r"(a[3]),
                   "r"(b[0]), "r"(b[1]));
}
__device__ __forceinline__ uint32_t pack2(unsigned short a, unsigned short b) {
    return (uint32_t)a | ((uint32_t)b << 16);
}
__device__ __forceinline__ void split_bf16(float f, unsigned short& h, unsigned short& l) {
    __nv_bfloat16 hb = __float2bfloat16(f);
    __nv_bfloat16 lb = __float2bfloat16(f - __bfloat162float(hb));
    h = *reinterpret_cast<unsigned short*>(&hb);
    l = *reinterpret_cast<unsigned short*>(&lb);
}

// ---------------------------------------------------------------------------
// Kernel A: row-normalize + hi/lo bf16 split of cn AND raw x.  One warp/row.
// ---------------------------------------------------------------------------
__global__ __launch_bounds__(256) void normalize_kernel(const float* __restrict__ x) {
    int row  = blockIdx.x * 8 + (threadIdx.x >> 5);
    int lane = threadIdx.x & 31;
    const float4* xr = (const float4*)(x + (size_t)row * EE);
    float4 v0 = xr[lane];
    float4 v1 = xr[lane + 32];
    float ss = v0.x*v0.x + v0.y*v0.y + v0.z*v0.z + v0.w*v0.w
             + v1.x*v1.x + v1.y*v1.y + v1.z*v1.z + v1.w*v1.w;
    #pragma unroll
    for (int off = 16; off; off >>= 1)
        ss += __shfl_xor_sync(0xffffffffu, ss, off);
    float inv = 1.0f / (sqrtf(ss) + EPSF);

    #pragma unroll
    for (int g = 0; g < 2; g++) {
        float4 v = g ? v1 : v0;
        float fr[4] = {v.x, v.y, v.z, v.w};
        unsigned short h[4], l[4], xh[4], xl[4];
        #pragma unroll
        for (int q = 0; q < 4; q++) {
            split_bf16(fr[q] * inv, h[q], l[q]);
            split_bf16(fr[q], xh[q], xl[q]);
        }
        size_t e = (size_t)row * EE + ((size_t)lane + (g ? 32 : 0)) * 4;
        *(uint2*)(g_hi  + e) = make_uint2(pack2(h[0],h[1]),  pack2(h[2],h[3]));
        *(uint2*)(g_lo  + e) = make_uint2(pack2(l[0],l[1]),  pack2(l[2],l[3]));
        *(uint2*)(g_xhi + e) = make_uint2(pack2(xh[0],xh[1]), pack2(xh[2],xh[3]));
        *(uint2*)(g_xlo + e) = make_uint2(pack2(xl[0],xl[1]), pack2(xl[2],xl[3]));
    }
}

// ---------------------------------------------------------------------------
// Kernel B: pair scores via mma.sync bf16 hi/lo (3-product fp32 emulation).
// CTA = (j, i, b), j < i.  C = cn_i @ cn_j^T (128x128x256), score = sum_c max_d C.
// ---------------------------------------------------------------------------
__global__ __launch_bounds__(256) void score_kernel() {
    int j = blockIdx.x, i = blockIdx.y, b = blockIdx.z;
    if (j >= i) return;

    extern __shared__ char sm[];
    uint32_t smb = smem_u32(sm);
    int tid = threadIdx.x, lane = tid & 31, wid = tid >> 5;
    int wm = wid & 1, wn = wid >> 1;

    const __nv_bfloat16* srcs[4];
    srcs[0] = g_hi + ((size_t)b * TT + (size_t)i * CSZ) * EE;   // Ah
    srcs[1] = g_lo + ((size_t)b * TT + (size_t)i * CSZ) * EE;   // Al
    srcs[2] = g_hi + ((size_t)b * TT + (size_t)j * CSZ) * EE;   // Bh
    srcs[3] = g_lo + ((size_t)b * TT + (size_t)j * CSZ) * EE;   // Bl

    float acc[4][4][4];
    #pragma unroll
    for (int mf = 0; mf < 4; mf++)
        #pragma unroll
        for (int nf = 0; nf < 4; nf++)
            #pragma unroll
            for (int q = 0; q < 4; q++) acc[mf][nf][q] = 0.0f;

    int g8  = lane & 7, sel = lane >> 3;
    int a_row = g8 + ((sel & 1) ? 8 : 0);
    int a_col = (sel & 2) ? 8 : 0;
    int b_row = g8 + ((sel >= 2) ? 8 : 0);
    int b_col = (sel & 1) ? 8 : 0;

    auto issue_stage = [&](int stage, int kt) {
        uint32_t sbase = smb + stage * STG;
        int k0 = kt * 32;
        #pragma unroll
        for (int t = 0; t < 8; t++) {
            int chunk = tid + t * 256;
            int tile  = chunk >> 9;
            int within = chunk & 511;
            int row = within >> 2;
            int seg = within & 3;
            cp16(sbase + tile * TILE_B + row * (LDB * 2) + seg * 16,
                 srcs[tile] + (size_t)row * EE + k0 + seg * 8);
        }
    };

    issue_stage(0, 0);
    cp_commit();

    for (int kt = 0; kt < 8; kt++) {
        int buf = kt & 1;
        if (kt < 7) {
            issue_stage(buf ^ 1, kt + 1);
            cp_commit();
            cp_wait<1>();
        } else {
            cp_wait<0>();
        }
        __syncthreads();

        uint32_t bAh = smb + buf * STG;
        uint32_t bAl = bAh + TILE_B;
        uint32_t bBh = bAh + 2 * TILE_B;
        uint32_t bBl = bAh + 3 * TILE_B;

        #pragma unroll
        for (int kk = 0; kk < 32; kk += 16) {
            uint32_t aH[4][4], aL[4][4], bH[4][2], bL[4][2];
            #pragma unroll
            for (int mf = 0; mf < 4; mf++) {
                uint32_t off = (uint32_t)((wm * 64 + mf * 16 + a_row) * (LDB * 2)
                                          + (kk + a_col) * 2);
                ldmx4(aH[mf], bAh + off);
                ldmx4(aL[mf], bAl + off);
            }
            #pragma unroll
            for (int p = 0; p < 2; p++) {
                uint32_t off = (uint32_t)((wn * 32 + p * 16 + b_row) * (LDB * 2)
                                          + (kk + b_col) * 2);
                uint32_t r[4];
                ldmx4(r, bBh + off);
                bH[2*p][0] = r[0]; bH[2*p][1] = r[1];
                bH[2*p+1][0] = r[2]; bH[2*p+1][1] = r[3];
                ldmx4(r, bBl + off);
                bL[2*p][0] = r[0]; bL[2*p][1] = r[1];
                bL[2*p+1][0] = r[2]; bL[2*p+1][1] = r[3];
            }
            #pragma unroll
            for (int mf = 0; mf < 4; mf++)
                #pragma unroll
                for (int nf = 0; nf < 4; nf++) {
                    mma16816(acc[mf][nf], aH[mf], bH[nf]);
                    mma16816(acc[mf][nf], aH[mf], bL[nf]);
                    mma16816(acc[mf][nf], aL[mf], bH[nf]);
                }
        }
        __syncthreads();
    }

    float* smax = (float*)(sm + OFF_MAX);
    #pragma unroll
    for (int mf = 0; mf < 4; mf++)
        #pragma unroll
        for (int h = 0; h < 2; h++) {
            float v = -3.402823466e38f;
            #pragma unroll
            for (int nf = 0; nf < 4; nf++) {
                v = fmaxf(v, acc[mf][nf][2*h]);
                v = fmaxf(v, acc[mf][nf][2*h + 1]);
            }
            v = fmaxf(v, __shfl_xor_sync(0xffffffffu, v, 1));
            v = fmaxf(v, __shfl_xor_sync(0xffffffffu, v, 2));
            if ((lane & 3) == 0)
                smax[wn * 128 + wm * 64 + mf * 16 + h * 8 + (lane >> 2)] = v;
        }
    __syncthreads();

    if (tid < 128) {
        float v = smax[tid];
        v = fmaxf(v, smax[128 + tid]);
        v = fmaxf(v, smax[256 + tid]);
        v = fmaxf(v, smax[384 + tid]);
        float ssum = v;
        #pragma unroll
        for (int off = 16; off; off >>= 1)
            ssum += __shfl_xor_sync(0xffffffffu, ssum, off);
        float* part = (float*)(sm + OFF_PART);
        if (lane == 0) part[wid] = ssum;
    }
    __syncthreads();
    if (tid == 0) {
        float* part = (float*)(sm + OFF_PART);
        g_scores[((size_t)b * NN + i) * NN + j] = part[0] + part[1] + part[2] + part[3];
    }
}

// ---------------------------------------------------------------------------
// Kernel C: top-7, weights, slot arrangement.  One warp per (b, i).
// ---------------------------------------------------------------------------
__global__ void topk_kernel() {
    int bi = blockIdx.x;
    int b = bi / NN, i = bi % NN;
    int lane = threadIdx.x;

    const float* srow = g_scores + ((size_t)b * NN + i) * NN;
    int j0 = lane, j1 = lane + 32;
    float v0 = (j0 < i) ? srow[j0] : -1e9f;
    float v1 = (j1 < i) ? srow[j1] : -1e9f;

    float vals[NSEL]; int idx[NSEL];
    for (int s = 0; s < NSEL; s++) {
        float bv; int bidx;
        if (v0 >= v1) { bv = v0; bidx = j0; } else { bv = v1; bidx = j1; }
        #pragma unroll
        for (int off = 16; off; off >>= 1) {
            float ov = __shfl_xor_sync(0xffffffffu, bv, off);
            int   oi = __shfl_xor_sync(0xffffffffu, bidx, off);
            if (ov > bv || (ov == bv && oi < bidx)) { bv = ov; bidx = oi; }
        }
        vals[s] = bv; idx[s] = bidx;
        if (j0 == bidx) v0 = -3.402823466e38f;
        if (j1 == bidx) v1 = -3.402823466e38f;
    }

    if (lane == 0) {
        int num_sel = (i < NSEL) ? i : NSEL;
        int vs = num_sel - 1;
        if (vs < 0) vs = 0;
        float vmin = vals[vs];
        float w[NSEL];
        for (int s = 0; s < NSEL; s++)
            w[s] = (s < num_sel) ? vals[s] / (vmin + EPSF) : 0.0f;
        int shift = NSEL - i; if (shift < 0) shift = 0;
        for (int t = 0; t < NSEL; t++) {
            int dst = ((size_t)b * NN + i) * NSEL + t;
            if (t >= shift) {
                g_selidx[dst] = idx[t - shift];
                g_selw[dst]   = w[t - shift];
            } else {
                g_selidx[dst] = 0;
                g_selw[dst]   = 0.0f;
            }
        }
    }
}

// ---------------------------------------------------------------------------
// Kernel D: out[b,n] = down_proj @ ext + chunk, via mma.sync bf16 hi/lo.
// CTA = (eh, n, b).  M=128 (c), N=128 (e-half), K=1024 (l).
// A = dp * w_slot, split hi/lo from fp32 at stage time (exact w scaling).
// B = raw-x hi/lo (precomputed), staged [l][e] via cp.async, ldmatrix.trans.
// ---------------------------------------------------------------------------
__global__ __launch_bounds__(256) void out_kernel_mma(const float* __restrict__ x,
                                                      const float* __restrict__ dp,
                                                      float* __restrict__ out) {
    int eh = blockIdx.x, n = blockIdx.y, b = blockIdx.z;

    extern __shared__ char sm[];
    uint32_t smb = smem_u32(sm);
    __shared__ int   s_idx[8];
    __shared__ float s_w[8];

    int tid = threadIdx.x, lane = tid & 31, wid = tid >> 5;
    int wm = wid & 1, wn = wid >> 1;
    int e0 = eh * 128;

    if (tid < NSEL) {
        s_idx[tid] = g_selidx[((size_t)b * NN + n) * NSEL + tid];
        s_w[tid]   = g_selw[((size_t)b * NN + n) * NSEL + tid];
    }
    if (tid == NSEL) { s_idx[NSEL] = n; s_w[NSEL] = 1.0f; }
    __syncthreads();

    const __nv_bfloat16* xhb = g_xhi + (size_t)b * TT * EE;
    const __nv_bfloat16* xlb = g_xlo + (size_t)b * TT * EE;

    // per-thread A staging geometry: 4 float4s (rows of dp)
    int arow[4], acol4[4];
    #pragma unroll
    for (int r = 0; r < 4; r++) {
        int idx = tid + r * 256;
        arow[r]  = idx >> 3;
        acol4[r] = idx & 7;
    }

    // B staging: issue cp.async for k-chunk kt into stage
    auto issue_B = [&](int stage, int kt) {
        uint32_t base = smb + stage * OSTG + 2 * OA_TILE;
        int l0 = kt * 32;
        int slot = l0 >> 7;
        int base_row = s_idx[slot] * CSZ + (l0 & 127);
        #pragma unroll
        for (int t = 0; t < 4; t++) {
            int idx = tid + t * 256;        // 0..1023
            int tile = idx >> 9;            // 0 = hi, 1 = lo
            int within = idx & 511;
            int row = within >> 4;          // 0..31
            int seg = within & 15;          // 16B segment
            const __nv_bfloat16* src = (tile ? xlb : xhb)
                + (size_t)(base_row + row) * EE + e0 + seg * 8;
            cp16(base + tile * OB_TILE + row * (LDE * 2) + seg * 16, src);
        }
    };

    // A staging: convert dp fp32 regs (pre-fetched) -> hi/lo smem
    auto store_A = [&](int stage, float4* av, float w) {
        uint32_t baseh = smb + stage * OSTG;
        uint32_t basel = baseh + OA_TILE;
        #pragma unroll
        for (int r = 0; r < 4; r++) {
            float f[4] = {av[r].x * w, av[r].y * w, av[r].z * w, av[r].w * w};
            unsigned short h[4], l[4];
            #pragma unroll
            for (int q = 0; q < 4; q++) split_bf16(f[q], h[q], l[q]);
            uint32_t off = (uint32_t)(arow[r] * (LDB * 2) + acol4[r] * 8);
            *(uint2*)(sm + (baseh - smb) + off) = make_uint2(pack2(h[0],h[1]), pack2(h[2],h[3]));
            *(uint2*)(sm + (basel - smb) + off) = make_uint2(pack2(l[0],l[1]), pack2(l[2],l[3]));
        }
    };
    auto fetch_A = [&](float4* av, int kt) {
        int l0 = kt * 32;
        #pragma unroll
        for (int r = 0; r < 4; r++)
            av[r] = *(const float4*)(dp + (size_t)arow[r] * LEXT + l0 + acol4[r] * 4);
    };

    float acc[4][4][4];
    #pragma unroll
    for (int mf = 0; mf < 4; mf++)
        #pragma unroll
        for (int nf = 0; nf < 4; nf++)
            #pragma unroll
            for (int q = 0; q < 4; q++) acc[mf][nf][q] = 0.0f;

    int g8  = lane & 7, sel = lane >> 3;
    int a_row = g8 + ((sel & 1) ? 8 : 0);
    int a_col = (sel & 2) ? 8 : 0;
    int bk_off = g8 + ((sel & 1) ? 8 : 0);   // k offset within chunk (trans)
    int bn_off = (sel & 2) ? 8 : 0;          // n offset

    // prologue: stage kt=0
    {
        float4 av[4];
        fetch_A(av, 0);
        issue_B(0, 0);
        cp_commit();
        store_A(0, av, s_w[0]);
        cp_wait<0>();
        __syncthreads();
    }

    for (int kt = 0; kt < 32; kt++) {
        int buf = kt & 1;
        float4 av[4];
        if (kt < 31) {
            fetch_A(av, kt + 1);
            issue_B(buf ^ 1, kt + 1);
            cp_commit();
        }

        uint32_t bAh = smb + buf * OSTG;
        uint32_t bAl = bAh + OA_TILE;
        uint32_t bBh = bAh + 2 * OA_TILE;
        uint32_t bBl = bBh + OB_TILE;

        #pragma unroll
        for (int kk = 0; kk < 32; kk += 16) {
            uint32_t aH[4][4], aL[4][4], bH[4][2], bL[4][2];
            #pragma unroll
            for (int mf = 0; mf < 4; mf++) {
                uint32_t off = (uint32_t)((wm * 64 + mf * 16 + a_row) * (LDB * 2)
                                          + (kk + a_col) * 2);
                ldmx4(aH[mf], bAh + off);
                ldmx4(aL[mf], bAl + off);
            }
            #pragma unroll
            for (int p = 0; p < 2; p++) {
                uint32_t off = (uint32_t)((kk + bk_off) * (LDE * 2)
                                          + (wn * 32 + p * 16 + bn_off) * 2);
                uint32_t r[4];
                ldmx4t(r, bBh + off);
                bH[2*p][0] = r[0]; bH[2*p][1] = r[1];
                bH[2*p+1][0] = r[2]; bH[2*p+1][1] = r[3];
                ldmx4t(r, bBl + off);
                bL[2*p][0] = r[0]; bL[2*p][1] = r[1];
                bL[2*p+1][0] = r[2]; bL[2*p+1][1] = r[3];
            }
            #pragma unroll
            for (int mf = 0; mf < 4; mf++)
                #pragma unroll
                for (int nf = 0; nf < 4; nf++) {
                    mma16816(acc[mf][nf], aH[mf], bH[nf]);
                    mma16816(acc[mf][nf], aH[mf], bL[nf]);
                    mma16816(acc[mf][nf], aL[mf], bH[nf]);
                }
        }

        if (kt < 31) store_A(buf ^ 1, av, s_w[(kt + 1) >> 2]);
        cp_wait<0>();
        __syncthreads();
    }

    // epilogue: add residual (chunk n) and store
    const float* xb = x + (size_t)b * TT * EE;
    #pragma unroll
    for (int mf = 0; mf < 4; mf++)
        #pragma unroll
        for (int h = 0; h < 2; h++) {
            int row = wm * 64 + mf * 16 + h * 8 + (lane >> 2);
            const float* resrow = xb + ((size_t)n * CSZ + row) * EE + e0;
            float* orow = out + ((size_t)b * TT + (size_t)n * CSZ + row) * EE + e0;
            #pragma unroll
            for (int nf = 0; nf < 4; nf++) {
                int col = wn * 32 + nf * 8 + (lane & 3) * 2;
                float2 res = *(const float2*)(resrow + col);
                float2 o;
                o.x = acc[mf][nf][2*h]     + res.x;
                o.y = acc[mf][nf][2*h + 1] + res.y;
                *(float2*)(orow + col) = o;
            }
        }
}

// ---------------------------------------------------------------------------
extern "C" void kernel_launch(void* const* d_in, const int* in_sizes, int n_in,
                              void* d_out, int out_size) {
    const float* x  = (const float*)d_in[0];
    const float* dp = (const float*)d_in[1];
    if (in_sizes[0] == CSZ * LEXT) {  // down_proj came first
        dp = (const float*)d_in[0];
        x  = (const float*)d_in[1];
    }
    float* out = (float*)d_out;

    cudaFuncSetAttribute(score_kernel,
                         cudaFuncAttributeMaxDynamicSharedMemorySize, SCORE_SMEM);
    cudaFuncSetAttribute(out_kernel_mma,
                         cudaFuncAttributeMaxDynamicSharedMemorySize, OUT_SMEM);

    normalize_kernel<<<(BB * TT) / 8, 256>>>(x);
    score_kernel<<<dim3(NN, NN, BB), 256, SCORE_SMEM>>>();
    topk_kernel<<<BB * NN, 32>>>();
    out_kernel_mma<<<dim3(2, NN, BB), 256, OUT_SMEM>>>(x, dp, out);
}